// round 14
// baseline (speedup 1.0000x reference)
#include <cuda_runtime.h>
#include <stdint.h>
#include <stddef.h>

#define T_TOK 4096
#define HDIM  1024
#define FDIM  2048
#define NEXP  8

// ---------------- scratch (__device__ globals: alloc-free) ----------------
__device__ int   g_cnt[NEXP];
__device__ int   g_tok[NEXP * T_TOK];
__device__ float g_wt [NEXP * T_TOK];
__device__ float g_h  [(size_t)NEXP * T_TOK * FDIM];   // silu(XW1)*XW3, tf32, k-perm
__device__ float g_xr [(size_t)T_TOK * HDIM];          // x tf32-rounded, k-perm
__device__ float g_w1t[(size_t)NEXP * FDIM * HDIM];    // w1^T [E][F][H], k-perm
__device__ float g_w3t[(size_t)NEXP * FDIM * HDIM];    // w3^T [E][F][H], k-perm
__device__ float g_w2t[(size_t)NEXP * HDIM * FDIM];    // w2^T [E][H][F], k-perm

// ---------------- helpers ----------------
__device__ __forceinline__ uint32_t smem_u32(const void* p) {
    uint32_t a;
    asm("{ .reg .u64 t; cvta.to.shared.u64 t, %1; cvt.u32.u64 %0, t; }" : "=r"(a) : "l"(p));
    return a;
}
__device__ __forceinline__ float rna_tf32(float f) {
    uint32_t r;
    asm("cvt.rna.tf32.f32 %0, %1;" : "=r"(r) : "f"(f));
    return __uint_as_float(r);
}
// logical k -> physical k within 16-blocks: phys = 4*(k%4) + k/4
__device__ __forceinline__ int perm16(int f) {
    return (f & ~15) | ((f & 3) << 2) | ((f >> 2) & 3);
}
// smem offset: row stride 128B (32 floats), 8 chunks of 16B, xor-swizzled
__device__ __forceinline__ uint32_t swoff(int row, int chunk) {
    return (uint32_t)(row * 128 + ((chunk ^ ((row & 1) << 2)) << 4));
}

#define CP_ASYNC16(dst, src) \
    asm volatile("cp.async.cg.shared.global [%0], [%1], 16;\n" :: "r"(dst), "l"(src))
#define CP_COMMIT() asm volatile("cp.async.commit_group;\n")
#define CP_WAIT0()  asm volatile("cp.async.wait_group 0;\n")

__device__ __forceinline__ void lds128(uint4& v, uint32_t addr) {
    asm volatile("ld.shared.v4.b32 {%0,%1,%2,%3}, [%4];"
                 : "=r"(v.x), "=r"(v.y), "=r"(v.z), "=r"(v.w) : "r"(addr));
}
__device__ __forceinline__ void mma8(float* d, uint32_t a0, uint32_t a1, uint32_t a2,
                                     uint32_t a3, uint32_t b0, uint32_t b1) {
    asm volatile(
        "mma.sync.aligned.m16n8k8.row.col.f32.tf32.tf32.f32 "
        "{%0,%1,%2,%3}, {%4,%5,%6,%7}, {%8,%9}, {%0,%1,%2,%3};\n"
        : "+f"(d[0]), "+f"(d[1]), "+f"(d[2]), "+f"(d[3])
        : "r"(a0), "r"(a1), "r"(a2), "r"(a3), "r"(b0), "r"(b1));
}
__device__ __forceinline__ float silu_mul_tf32(float d1, float d3) {
    return rna_tf32(d1 / (1.f + __expf(-d1)) * d3);
}

// ---------------- init ----------------
__global__ void init_counts() {
    if (threadIdx.x < NEXP) g_cnt[threadIdx.x] = 0;
}

// ---------------- router ----------------
__global__ void router_kernel(const float* __restrict__ x,
                              const float* __restrict__ gw,
                              float* __restrict__ logits_out,
                              int write_logits)
{
    int tok  = (blockIdx.x * blockDim.x + threadIdx.x) >> 5;
    int lane = threadIdx.x & 31;
    if (tok >= T_TOK) return;
    const float* xr = x + (size_t)tok * HDIM;

    float acc[NEXP];
#pragma unroll
    for (int e = 0; e < NEXP; e++) acc[e] = 0.f;
    for (int h = lane; h < HDIM; h += 32) {
        float xv = xr[h];
#pragma unroll
        for (int e = 0; e < NEXP; e++) acc[e] = fmaf(xv, gw[e * HDIM + h], acc[e]);
    }
#pragma unroll
    for (int e = 0; e < NEXP; e++) {
#pragma unroll
        for (int off = 16; off > 0; off >>= 1)
            acc[e] += __shfl_xor_sync(0xffffffffu, acc[e], off);
    }
    if (lane == 0) {
        if (write_logits) {
#pragma unroll
            for (int e = 0; e < NEXP; e++) logits_out[tok * NEXP + e] = acc[e];
        }
        float mx = acc[0];
#pragma unroll
        for (int e = 1; e < NEXP; e++) mx = fmaxf(mx, acc[e]);
        float p[NEXP], s = 0.f;
#pragma unroll
        for (int e = 0; e < NEXP; e++) { p[e] = __expf(acc[e] - mx); s += p[e]; }
        float inv = 1.f / s;
#pragma unroll
        for (int e = 0; e < NEXP; e++) p[e] *= inv;

        int i1 = 0; float m1 = p[0];
#pragma unroll
        for (int e = 1; e < NEXP; e++) if (p[e] > m1) { m1 = p[e]; i1 = e; }
        int i2 = -1; float m2 = -1.f;
#pragma unroll
        for (int e = 0; e < NEXP; e++) {
            if (e == i1) continue;
            if (p[e] > m2) { m2 = p[e]; i2 = e; }
        }
        int pos1 = atomicAdd(&g_cnt[i1], 1);
        g_tok[i1 * T_TOK + pos1] = tok;  g_wt[i1 * T_TOK + pos1] = m1;
        int pos2 = atomicAdd(&g_cnt[i2], 1);
        g_tok[i2 * T_TOK + pos2] = tok;  g_wt[i2 * T_TOK + pos2] = m2;
    }
}

// ---------------- fused pre-pass ------------------------------------------
// grid (512, 25), block 256.
//  by in [0,8)  : w1 expert by         (K=1024, N=2048)  4 k-tiles/block
//  by in [8,16) : w3 expert by-8
//  by in [16,24): w2 expert by-16      (K=2048, N=1024)
//  by == 24     : x tf32-round+k-perm  32 floats/thread
__global__ void prepass_kernel(const float* __restrict__ x,
                               const float* __restrict__ w1,
                               const float* __restrict__ w3,
                               const float* __restrict__ w2)
{
    const int by = blockIdx.y;
    const int bx = blockIdx.x;
    if (by == 24) {
        int base = (bx * 256 + threadIdx.x) * 32;
#pragma unroll
        for (int q = 0; q < 8; q++) {
            int p = base + q * 4;
            int grp = p & ~15, j = (p >> 2) & 3;
            float4 o;
            o.x = rna_tf32(x[grp + j]);
            o.y = rna_tf32(x[grp + 4 + j]);
            o.z = rna_tf32(x[grp + 8 + j]);
            o.w = rna_tf32(x[grp + 12 + j]);
            *(float4*)(g_xr + p) = o;
        }
        return;
    }

    __shared__ float t[4][32][33];
    const float* in;
    float* out;
    int K, N, n0, k0;
    if (by < 16) {
        K = HDIM; N = FDIM;
        int e = by & 7;
        in  = ((by < 8) ? w1 : w3) + (size_t)e * K * N;
        out = ((by < 8) ? g_w1t : g_w3t) + (size_t)e * K * N;
        n0 = (bx & 63) * 32; k0 = (bx >> 6) * 128;   // 64 n-tiles x 8 k-quads
    } else {
        K = FDIM; N = HDIM;
        int e = by - 16;
        in  = w2 + (size_t)e * K * N;
        out = g_w2t + (size_t)e * K * N;
        n0 = (bx & 31) * 32; k0 = (bx >> 5) * 128;   // 32 n-tiles x 16 k-quads
    }

    int kr = threadIdx.x >> 3;            // 0..31
    int nc = (threadIdx.x & 7) * 4;
    float4 v[4];
#pragma unroll
    for (int q = 0; q < 4; q++)
        v[q] = *(const float4*)(in + (size_t)(k0 + q * 32 + kr) * N + n0 + nc);
#pragma unroll
    for (int q = 0; q < 4; q++) {
        t[q][kr][nc] = v[q].x; t[q][kr][nc + 1] = v[q].y;
        t[q][kr][nc + 2] = v[q].z; t[q][kr][nc + 3] = v[q].w;
    }
    __syncthreads();

    int nr = threadIdx.x >> 3;
    int c  = threadIdx.x & 7;
    int g  = (c >> 2) * 16, j = c & 3;
#pragma unroll
    for (int q = 0; q < 4; q++) {
        float4 o;
        o.x = rna_tf32(t[q][g + j     ][nr]);
        o.y = rna_tf32(t[q][g + 4 + j ][nr]);
        o.z = rna_tf32(t[q][g + 8 + j ][nr]);
        o.w = rna_tf32(t[q][g + 12 + j][nr]);
        *(float4*)(out + (size_t)(n0 + nr) * K + k0 + q * 32 + g + 4 * j) = o;
    }
}

// =====================================================================
// GEMM13 fused: h = silu(Xg @ W1) * (Xg @ W3)
// BM=128, BN=64, BK=32, 256 thr (8 warps 4m x 2n). Warp: 32r x 32c x 2 mats.
// smem/stage (32KB): A[0,16K) B1[16K,24K) B3[24K,32K). 2 stages, wait0.
// Epilogue: shfl-pack -> 8 STG.128/thread (phys layout, bypasses perm16).
// =====================================================================
__global__ void __launch_bounds__(256, 2)
moe_gemm13()
{
    const int e   = blockIdx.z;
    const int cnt = g_cnt[e];
    const int m0  = blockIdx.x * 128;
    if (m0 >= cnt) return;
    const int n0  = blockIdx.y * 64;

    extern __shared__ char dsm[];
    const uint32_t sb = (smem_u32(dsm) + 127u) & ~127u;
    __shared__ const float* s_arow[128];

    const int tid  = threadIdx.x;
    const int warp = tid >> 5;
    const int lane = tid & 31;
    const int qr   = lane >> 2;
    const int qc   = lane & 3;
    const int rq   = warp & 3;
    const int cf   = warp >> 2;

    if (tid < 128) {
        int mm = min(m0 + tid, cnt - 1);
        s_arow[tid] = g_xr + (size_t)g_tok[e * T_TOK + mm] * HDIM;
    }
    __syncthreads();

    const float* b1b = g_w1t + (size_t)e * FDIM * HDIM + (size_t)n0 * HDIM;
    const float* b3b = g_w3t + (size_t)e * FDIM * HDIM + (size_t)n0 * HDIM;

    const int ch  = tid & 7;
    const int rr  = tid >> 3;       // 0..31
    const float* pA[4]; uint32_t dA[4];
#pragma unroll
    for (int i = 0; i < 4; i++) {
        int row = i * 32 + rr;
        pA[i] = s_arow[row] + ch * 4;
        dA[i] = sb + swoff(row, ch);
    }
    const float* pB1[2]; const float* pB3[2]; uint32_t dB[2];
#pragma unroll
    for (int i = 0; i < 2; i++) {
        int row = i * 32 + rr;      // 0..63
        pB1[i] = b1b + (size_t)row * HDIM + ch * 4;
        pB3[i] = b3b + (size_t)row * HDIM + ch * 4;
        dB[i]  = sb + 16384u + swoff(row, ch);
    }

    const uint32_t swsel = (uint32_t)((qc ^ ((qr & 1) << 2)) << 4);
    const uint32_t aBase = sb + (uint32_t)((rq * 32 + qr) << 7) + swsel;
    const uint32_t bBase = sb + 16384u + (uint32_t)((cf * 32 + qr) << 7) + swsel;

#define LOAD13(stc_, ko_) do {                                            \
    _Pragma("unroll")                                                     \
    for (int i_ = 0; i_ < 4; i_++)                                        \
        CP_ASYNC16(dA[i_] + (stc_), pA[i_] + (ko_));                      \
    _Pragma("unroll")                                                     \
    for (int i_ = 0; i_ < 2; i_++) {                                      \
        CP_ASYNC16(dB[i_] + (stc_),         pB1[i_] + (ko_));             \
        CP_ASYNC16(dB[i_] + 8192u + (stc_), pB3[i_] + (ko_));             \
    }                                                                     \
    CP_COMMIT();                                                          \
} while (0)

#define COMPUTE13(stc_) do {                                                        \
    const uint32_t aS0 = aBase + (stc_), bS0 = bBase + (stc_);                      \
    _Pragma("unroll")                                                               \
    for (int s = 0; s < 2; s++) {                                                   \
        const uint32_t aA = s ? (aS0 ^ 64u) : aS0;                                  \
        const uint32_t bB = s ? (bS0 ^ 64u) : bS0;                                  \
        uint4 alo[2], ahi[2];                                                       \
        lds128(alo[0], aA);           lds128(ahi[0], aA + 1024u);                   \
        lds128(alo[1], aA + 2048u);   lds128(ahi[1], aA + 3072u);                   \
        _Pragma("unroll")                                                           \
        for (int nt = 0; nt < 4; nt++) {                                            \
            uint4 b1v, b3v;                                                         \
            lds128(b1v, bB + (uint32_t)(nt * 1024));                                \
            lds128(b3v, bB + (uint32_t)(8192 + nt * 1024));                         \
            _Pragma("unroll")                                                       \
            for (int mt = 0; mt < 2; mt++) {                                        \
                mma8(acc1[mt][nt], alo[mt].x, ahi[mt].x, alo[mt].y, ahi[mt].y, b1v.x, b1v.y); \
                mma8(acc1[mt][nt], alo[mt].z, ahi[mt].z, alo[mt].w, ahi[mt].w, b1v.z, b1v.w); \
                mma8(acc3[mt][nt], alo[mt].x, ahi[mt].x, alo[mt].y, ahi[mt].y, b3v.x, b3v.y); \
                mma8(acc3[mt][nt], alo[mt].z, ahi[mt].z, alo[mt].w, ahi[mt].w, b3v.z, b3v.w); \
            }                                                                       \
        }                                                                           \
    }                                                                               \
} while (0)

    float acc1[2][4][4], acc3[2][4][4];
#pragma unroll
    for (int mt = 0; mt < 2; mt++)
#pragma unroll
        for (int nt = 0; nt < 4; nt++)
#pragma unroll
            for (int i = 0; i < 4; i++) { acc1[mt][nt][i] = 0.f; acc3[mt][nt][i] = 0.f; }

    LOAD13(0u, 0);
#pragma unroll
    for (int i = 0; i < 4; i++) pA[i] += 32;
    pB1[0] += 32; pB1[1] += 32; pB3[0] += 32; pB3[1] += 32;

    const int NT = HDIM / 32;   // 32 (even)
    for (int t = 0; t < NT; t += 2) {
        CP_WAIT0();
        __syncthreads();
        LOAD13(32768u, 0);
        COMPUTE13(0u);
        CP_WAIT0();
        __syncthreads();
        if (t + 2 < NT) LOAD13(0u, 32);
        COMPUTE13(32768u);
#pragma unroll
        for (int i = 0; i < 4; i++) pA[i] += 64;
        pB1[0] += 64; pB1[1] += 64; pB3[0] += 64; pB3[1] += 64;
    }

    // epilogue: shfl-pack to phys-contiguous float4 stores.
    // phys block layout: p = 4*(l%4)+l/4 for l = (nt%2)*8 + qc*2 + b.
    // lanes qc<->qc^2 exchange b-complement values (same qr => same row).
    {
        const int jj = (qc & 1) * 2 + (qc >> 1);
        const bool low = (qc < 2);
#pragma unroll
        for (int mt = 0; mt < 2; mt++) {
#pragma unroll
            for (int h = 0; h < 2; h++) {
                int m = m0 + rq * 32 + mt * 16 + qr + 8 * h;
                bool ok = (m < cnt);
                float* hrow = g_h + ((size_t)e * T_TOK + m) * FDIM + n0 + cf * 32;
#pragma unroll
                for (int k = 0; k < 2; k++) {
                    float v00 = silu_mul_tf32(acc1[mt][2*k  ][2*h  ], acc3[mt][2*k  ][2*h  ]);
                    float v01 = silu_mul_tf32(acc1[mt][2*k  ][2*h+1], acc3[mt][2*k  ][2*h+1]);
                    float v10 = silu_mul_tf32(acc1[mt][2*k+1][2*h  ], acc3[mt][2*k+1][2*h  ]);
                    float v11 = silu_mul_tf32(acc1[mt][2*k+1][2*h+1], acc3[mt][2*k+1][2*h+1]);
                    float r0 = __shfl_xor_sync(0xffffffffu, low ? v01 : v00, 2);
                    float r1 = __shfl_xor_sync(0xffffffffu, low ? v11 : v10, 2);
                    float4 o;
                    if (low) { o.x = v00; o.y = r0;  o.z = v10; o.w = r1;  }
                    else     { o.x = r0;  o.y = v01; o.z = r1;  o.w = v11; }
                    if (ok) *(float4*)(hrow + k * 16 + 4 * jj) = o;
                }
            }
        }
    }
#undef LOAD13
#undef COMPUTE13
}

// =====================================================================
// GEMM2: y += wt * (h @ W2).  BM=128, BN=128, BK=32, 256 thr (4m x 2n).
// Warp: 32r x 64c. smem/stage (32KB): A[0,16K) B[16K,32K). 2 stages, wait0.
// =====================================================================
__global__ void __launch_bounds__(256, 2)
moe_gemm2(float* __restrict__ y)
{
    const int e   = blockIdx.z;
    const int cnt = g_cnt[e];
    const int m0  = blockIdx.x * 128;
    if (m0 >= cnt) return;
    const int n0  = blockIdx.y * 128;

    extern __shared__ char dsm[];
    const uint32_t sb = (smem_u32(dsm) + 127u) & ~127u;
    __shared__ const float* s_arow[128];

    const int tid  = threadIdx.x;
    const int warp = tid >> 5;
    const int lane = tid & 31;
    const int qr   = lane >> 2;
    const int qc   = lane & 3;
    const int rq   = warp & 3;
    const int cf   = warp >> 2;

    if (tid < 128) {
        int mm = min(m0 + tid, cnt - 1);
        s_arow[tid] = g_h + ((size_t)e * T_TOK + mm) * FDIM;
    }
    __syncthreads();

    const float* bb = g_w2t + (size_t)e * HDIM * FDIM + (size_t)n0 * FDIM;

    const int ch = tid & 7;
    const int rr = tid >> 3;
    const float* pA[4]; uint32_t dA[4]; const float* pB[4]; uint32_t dB[4];
#pragma unroll
    for (int i = 0; i < 4; i++) {
        int row = i * 32 + rr;
        pA[i] = s_arow[row] + ch * 4;
        dA[i] = sb + swoff(row, ch);
        pB[i] = bb + (size_t)row * FDIM + ch * 4;
        dB[i] = sb + 16384u + swoff(row, ch);
    }

    const uint32_t swsel = (uint32_t)((qc ^ ((qr & 1) << 2)) << 4);
    const uint32_t aBase = sb + (uint32_t)((rq * 32 + qr) << 7) + swsel;
    const uint32_t bBase = sb + 16384u + (uint32_t)((cf * 64 + qr) << 7) + swsel;

#define LOAD2(stc_, ko_) do {                                             \
    _Pragma("unroll")                                                     \
    for (int i_ = 0; i_ < 4; i_++) {                                      \
        CP_ASYNC16(dA[i_] + (stc_), pA[i_] + (ko_));                      \
        CP_ASYNC16(dB[i_] + (stc_), pB[i_] + (ko_));                      \
    }                                                                     \
    CP_COMMIT();                                                          \
} while (0)

#define COMPUTE2(stc_) do {                                                         \
    const uint32_t aS0 = aBase + (stc_), bS0 = bBase + (stc_);                      \
    _Pragma("unroll")                                                               \
    for (int s = 0; s < 2; s++) {                                                   \
        const uint32_t aA = s ? (aS0 ^ 64u) : aS0;                                  \
        const uint32_t bB = s ? (bS0 ^ 64u) : bS0;                                  \
        uint4 alo[2], ahi[2];                                                       \
        lds128(alo[0], aA);           lds128(ahi[0], aA + 1024u);                   \
        lds128(alo[1], aA + 2048u);   lds128(ahi[1], aA + 3072u);                   \
        _Pragma("unroll")                                                           \
        for (int nt = 0; nt < 8; nt++) {                                            \
            uint4 bv;                                                               \
            lds128(bv, bB + (uint32_t)(nt * 1024));                                 \
            _Pragma("unroll")                                                       \
            for (int mt = 0; mt < 2; mt++) {                                        \
                mma8(acc[mt][nt], alo[mt].x, ahi[mt].x, alo[mt].y, ahi[mt].y, bv.x, bv.y); \
                mma8(acc[mt][nt], alo[mt].z, ahi[mt].z, alo[mt].w, ahi[mt].w, bv.z, bv.w); \
            }                                                                       \
        }                                                                           \
    }                                                                               \
} while (0)

    float acc[2][8][4];
#pragma unroll
    for (int mt = 0; mt < 2; mt++)
#pragma unroll
        for (int nt = 0; nt < 8; nt++)
#pragma unroll
            for (int i = 0; i < 4; i++) acc[mt][nt][i] = 0.f;

    LOAD2(0u, 0);
#pragma unroll
    for (int i = 0; i < 4; i++) { pA[i] += 32; pB[i] += 32; }

    const int NT = FDIM / 32;   // 64 (even)
    for (int t = 0; t < NT; t += 2) {
        CP_WAIT0();
        __syncthreads();
        LOAD2(32768u, 0);
        COMPUTE2(0u);
        CP_WAIT0();
        __syncthreads();
        if (t + 2 < NT) LOAD2(0u, 32);
        COMPUTE2(32768u);
#pragma unroll
        for (int i = 0; i < 4; i++) { pA[i] += 64; pB[i] += 64; }
    }

    // epilogue: y[tok] += wt * D (REDG atomics - measured cheap)
#pragma unroll
    for (int mt = 0; mt < 2; mt++) {
#pragma unroll
        for (int h = 0; h < 2; h++) {
            int m = m0 + rq * 32 + mt * 16 + qr + 8 * h;
            if (m >= cnt) continue;
            float w   = g_wt [e * T_TOK + m];
            int   tok = g_tok[e * T_TOK + m];
            float* yrow = y + (size_t)tok * HDIM + n0 + cf * 64;
#pragma unroll
            for (int nt = 0; nt < 8; nt++) {
#pragma unroll
                for (int b = 0; b < 2; b++)
                    atomicAdd(yrow + nt * 8 + qc * 2 + b, w * acc[mt][nt][2 * h + b]);
            }
        }
    }
#undef LOAD2
#undef COMPUTE2
}

// ---------------- launch ----------------
extern "C" void kernel_launch(void* const* d_in, const int* in_sizes, int n_in,
                              void* d_out, int out_size)
{
    const float* x  = (const float*)d_in[0];   // [2,2048,1024]
    const float* gw = (const float*)d_in[1];   // [8,1024]
    const float* w1 = (const float*)d_in[2];   // [8,1024,2048]
    const float* w3 = (const float*)d_in[3];   // [8,1024,2048]
    const float* w2 = (const float*)d_in[4];   // [8,2048,1024]
    float* out = (float*)d_out;

    const int SMEM = 2 * 32768 + 128;   // 65664
    cudaFuncSetAttribute(moe_gemm13, cudaFuncAttributeMaxDynamicSharedMemorySize, SMEM);
    cudaFuncSetAttribute(moe_gemm2,  cudaFuncAttributeMaxDynamicSharedMemorySize, SMEM);

    cudaMemsetAsync(out, 0, (size_t)T_TOK * HDIM * sizeof(float));
    init_counts<<<1, 32>>>();

    int write_logits = (out_size >= T_TOK * HDIM + T_TOK * NEXP) ? 1 : 0;
    router_kernel<<<T_TOK / 4, 128>>>(x, gw, out + (size_t)T_TOK * HDIM, write_logits);

    prepass_kernel<<<dim3(512, 25), 256>>>(x, w1, w3, w2);

    moe_gemm13<<<dim3(T_TOK / 128, FDIM / 64, NEXP), 256, SMEM>>>();
    moe_gemm2 <<<dim3(T_TOK / 128, HDIM / 128, NEXP), 256, SMEM>>>(out);
}

// round 15
// speedup vs baseline: 1.0798x; 1.0798x over previous
#include <cuda_runtime.h>
#include <stdint.h>
#include <stddef.h>

#define T_TOK 4096
#define HDIM  1024
#define FDIM  2048
#define NEXP  8

// ---------------- scratch (__device__ globals: alloc-free) ----------------
__device__ int   g_cnt[NEXP];
__device__ int   g_tok[NEXP * T_TOK];
__device__ float g_wt [NEXP * T_TOK];
__device__ float g_h  [(size_t)NEXP * T_TOK * FDIM];   // silu(XW1)*XW3, tf32, k-perm
__device__ float g_xr [(size_t)T_TOK * HDIM];          // x tf32-rounded, k-perm
__device__ float g_w1t[(size_t)NEXP * FDIM * HDIM];    // w1^T [E][F][H], k-perm
__device__ float g_w3t[(size_t)NEXP * FDIM * HDIM];    // w3^T [E][F][H], k-perm
__device__ float g_w2t[(size_t)NEXP * HDIM * FDIM];    // w2^T [E][H][F], k-perm

// ---------------- helpers ----------------
__device__ __forceinline__ uint32_t smem_u32(const void* p) {
    uint32_t a;
    asm("{ .reg .u64 t; cvta.to.shared.u64 t, %1; cvt.u32.u64 %0, t; }" : "=r"(a) : "l"(p));
    return a;
}
__device__ __forceinline__ float rna_tf32(float f) {
    uint32_t r;
    asm("cvt.rna.tf32.f32 %0, %1;" : "=r"(r) : "f"(f));
    return __uint_as_float(r);
}
// logical k -> physical k within 16-blocks: phys = 4*(k%4) + k/4
__device__ __forceinline__ int perm16(int f) {
    return (f & ~15) | ((f & 3) << 2) | ((f >> 2) & 3);
}
// smem offset: row stride 128B (32 floats), 8 chunks of 16B, xor-swizzled
__device__ __forceinline__ uint32_t swoff(int row, int chunk) {
    return (uint32_t)(row * 128 + ((chunk ^ ((row & 1) << 2)) << 4));
}

#define CP_ASYNC16(dst, src) \
    asm volatile("cp.async.cg.shared.global [%0], [%1], 16;\n" :: "r"(dst), "l"(src))
#define CP_COMMIT() asm volatile("cp.async.commit_group;\n")
#define CP_WAIT0()  asm volatile("cp.async.wait_group 0;\n")

__device__ __forceinline__ void lds128(uint4& v, uint32_t addr) {
    asm volatile("ld.shared.v4.b32 {%0,%1,%2,%3}, [%4];"
                 : "=r"(v.x), "=r"(v.y), "=r"(v.z), "=r"(v.w) : "r"(addr));
}
__device__ __forceinline__ void mma8(float* d, uint32_t a0, uint32_t a1, uint32_t a2,
                                     uint32_t a3, uint32_t b0, uint32_t b1) {
    asm volatile(
        "mma.sync.aligned.m16n8k8.row.col.f32.tf32.tf32.f32 "
        "{%0,%1,%2,%3}, {%4,%5,%6,%7}, {%8,%9}, {%0,%1,%2,%3};\n"
        : "+f"(d[0]), "+f"(d[1]), "+f"(d[2]), "+f"(d[3])
        : "r"(a0), "r"(a1), "r"(a2), "r"(a3), "r"(b0), "r"(b1));
}
__device__ __forceinline__ float silu_mul_tf32(float d1, float d3) {
    return rna_tf32(d1 / (1.f + __expf(-d1)) * d3);
}

// ---------------- init ----------------
__global__ void init_counts() {
    if (threadIdx.x < NEXP) g_cnt[threadIdx.x] = 0;
}

// ---------------- router ----------------
__global__ void router_kernel(const float* __restrict__ x,
                              const float* __restrict__ gw,
                              float* __restrict__ logits_out,
                              int write_logits)
{
    int tok  = (blockIdx.x * blockDim.x + threadIdx.x) >> 5;
    int lane = threadIdx.x & 31;
    if (tok >= T_TOK) return;
    const float* xr = x + (size_t)tok * HDIM;

    float acc[NEXP];
#pragma unroll
    for (int e = 0; e < NEXP; e++) acc[e] = 0.f;
    for (int h = lane; h < HDIM; h += 32) {
        float xv = xr[h];
#pragma unroll
        for (int e = 0; e < NEXP; e++) acc[e] = fmaf(xv, gw[e * HDIM + h], acc[e]);
    }
#pragma unroll
    for (int e = 0; e < NEXP; e++) {
#pragma unroll
        for (int off = 16; off > 0; off >>= 1)
            acc[e] += __shfl_xor_sync(0xffffffffu, acc[e], off);
    }
    if (lane == 0) {
        if (write_logits) {
#pragma unroll
            for (int e = 0; e < NEXP; e++) logits_out[tok * NEXP + e] = acc[e];
        }
        float mx = acc[0];
#pragma unroll
        for (int e = 1; e < NEXP; e++) mx = fmaxf(mx, acc[e]);
        float p[NEXP], s = 0.f;
#pragma unroll
        for (int e = 0; e < NEXP; e++) { p[e] = __expf(acc[e] - mx); s += p[e]; }
        float inv = 1.f / s;
#pragma unroll
        for (int e = 0; e < NEXP; e++) p[e] *= inv;

        int i1 = 0; float m1 = p[0];
#pragma unroll
        for (int e = 1; e < NEXP; e++) if (p[e] > m1) { m1 = p[e]; i1 = e; }
        int i2 = -1; float m2 = -1.f;
#pragma unroll
        for (int e = 0; e < NEXP; e++) {
            if (e == i1) continue;
            if (p[e] > m2) { m2 = p[e]; i2 = e; }
        }
        int pos1 = atomicAdd(&g_cnt[i1], 1);
        g_tok[i1 * T_TOK + pos1] = tok;  g_wt[i1 * T_TOK + pos1] = m1;
        int pos2 = atomicAdd(&g_cnt[i2], 1);
        g_tok[i2 * T_TOK + pos2] = tok;  g_wt[i2 * T_TOK + pos2] = m2;
    }
}

// ---------------- fused pre-pass (R12 config: (1024,25), 2 tiles) ---------
__global__ void prepass_kernel(const float* __restrict__ x,
                               const float* __restrict__ w1,
                               const float* __restrict__ w3,
                               const float* __restrict__ w2)
{
    const int by = blockIdx.y;
    const int bx = blockIdx.x;
    if (by == 24) {
        int base = (bx * 256 + threadIdx.x) * 16;
#pragma unroll
        for (int q = 0; q < 4; q++) {
            int p = base + q * 4;
            int grp = p & ~15, j = (p >> 2) & 3;
            float4 o;
            o.x = rna_tf32(x[grp + j]);
            o.y = rna_tf32(x[grp + 4 + j]);
            o.z = rna_tf32(x[grp + 8 + j]);
            o.w = rna_tf32(x[grp + 12 + j]);
            *(float4*)(g_xr + p) = o;
        }
        return;
    }

    __shared__ float t[2][32][33];
    const float* in;
    float* out;
    int K, N, n0, k0;
    if (by < 16) {
        K = HDIM; N = FDIM;
        int e = by & 7;
        in  = ((by < 8) ? w1 : w3) + (size_t)e * K * N;
        out = ((by < 8) ? g_w1t : g_w3t) + (size_t)e * K * N;
        n0 = (bx & 63) * 32; k0 = (bx >> 6) * 64;
    } else {
        K = FDIM; N = HDIM;
        int e = by - 16;
        in  = w2 + (size_t)e * K * N;
        out = g_w2t + (size_t)e * K * N;
        n0 = (bx & 31) * 32; k0 = (bx >> 5) * 64;
    }

    int kr = threadIdx.x >> 3;            // 0..31
    int nc = (threadIdx.x & 7) * 4;
    float4 v0 = *(const float4*)(in + (size_t)(k0 + kr) * N + n0 + nc);
    float4 v1 = *(const float4*)(in + (size_t)(k0 + 32 + kr) * N + n0 + nc);
    t[0][kr][nc] = v0.x; t[0][kr][nc + 1] = v0.y; t[0][kr][nc + 2] = v0.z; t[0][kr][nc + 3] = v0.w;
    t[1][kr][nc] = v1.x; t[1][kr][nc + 1] = v1.y; t[1][kr][nc + 2] = v1.z; t[1][kr][nc + 3] = v1.w;
    __syncthreads();

    int nr = threadIdx.x >> 3;
    int c  = threadIdx.x & 7;
    int g  = (c >> 2) * 16, j = c & 3;
#pragma unroll
    for (int q = 0; q < 2; q++) {
        float4 o;
        o.x = rna_tf32(t[q][g + j     ][nr]);
        o.y = rna_tf32(t[q][g + 4 + j ][nr]);
        o.z = rna_tf32(t[q][g + 8 + j ][nr]);
        o.w = rna_tf32(t[q][g + 12 + j][nr]);
        *(float4*)(out + (size_t)(n0 + nr) * K + k0 + q * 32 + g + 4 * j) = o;
    }
}

// =====================================================================
// GEMM13 fused: h = silu(Xg @ W1) * (Xg @ W3)
// BM=64, BN=64, BK=32, 128 thr (4 warps 2m x 2n). Warp: 32r x 32c x 2 mats.
// smem/stage (24KB): A[0,8K) B1[8K,16K) B3[16K,24K). 2 stages, wait0.
// 4 CTAs/SM -> 4 independent barrier domains (same 16 warps/SM).
// =====================================================================
__global__ void __launch_bounds__(128, 4)
moe_gemm13()
{
    const int e   = blockIdx.z;
    const int cnt = g_cnt[e];
    const int m0  = blockIdx.x * 64;
    if (m0 >= cnt) return;
    const int n0  = blockIdx.y * 64;

    extern __shared__ char dsm[];
    const uint32_t sb = (smem_u32(dsm) + 127u) & ~127u;
    __shared__ const float* s_arow[64];

    const int tid  = threadIdx.x;
    const int warp = tid >> 5;
    const int lane = tid & 31;
    const int qr   = lane >> 2;
    const int qc   = lane & 3;
    const int rq   = warp & 1;     // 2 warps in M
    const int cf   = warp >> 1;    // 2 warps in N

    if (tid < 64) {
        int mm = min(m0 + tid, cnt - 1);
        s_arow[tid] = g_xr + (size_t)g_tok[e * T_TOK + mm] * HDIM;
    }
    __syncthreads();

    const float* b1b = g_w1t + (size_t)e * FDIM * HDIM + (size_t)n0 * HDIM;
    const float* b3b = g_w3t + (size_t)e * FDIM * HDIM + (size_t)n0 * HDIM;

    const int ch  = tid & 7;
    const int rr  = tid >> 3;       // 0..15
    const float* pA[4]; uint32_t dA[4];
    const float* pB1[4]; const float* pB3[4]; uint32_t dB[4];
#pragma unroll
    for (int i = 0; i < 4; i++) {
        int row = i * 16 + rr;      // 0..63
        pA[i]  = s_arow[row] + ch * 4;
        dA[i]  = sb + swoff(row, ch);
        pB1[i] = b1b + (size_t)row * HDIM + ch * 4;
        pB3[i] = b3b + (size_t)row * HDIM + ch * 4;
        dB[i]  = sb + 8192u + swoff(row, ch);
    }

    const uint32_t swsel = (uint32_t)((qc ^ ((qr & 1) << 2)) << 4);
    const uint32_t aBase = sb + (uint32_t)((rq * 32 + qr) << 7) + swsel;
    const uint32_t bBase = sb + 8192u + (uint32_t)((cf * 32 + qr) << 7) + swsel;

#define LOAD13(stc_, ko_) do {                                            \
    _Pragma("unroll")                                                     \
    for (int i_ = 0; i_ < 4; i_++) {                                      \
        CP_ASYNC16(dA[i_] + (stc_),         pA[i_]  + (ko_));             \
        CP_ASYNC16(dB[i_] + (stc_),         pB1[i_] + (ko_));             \
        CP_ASYNC16(dB[i_] + 8192u + (stc_), pB3[i_] + (ko_));             \
    }                                                                     \
    CP_COMMIT();                                                          \
} while (0)

#define COMPUTE13(stc_) do {                                                        \
    const uint32_t aS0 = aBase + (stc_), bS0 = bBase + (stc_);                      \
    _Pragma("unroll")                                                               \
    for (int s = 0; s < 2; s++) {                                                   \
        const uint32_t aA = s ? (aS0 ^ 64u) : aS0;                                  \
        const uint32_t bB = s ? (bS0 ^ 64u) : bS0;                                  \
        uint4 alo[2], ahi[2];                                                       \
        lds128(alo[0], aA);           lds128(ahi[0], aA + 1024u);                   \
        lds128(alo[1], aA + 2048u);   lds128(ahi[1], aA + 3072u);                   \
        _Pragma("unroll")                                                           \
        for (int nt = 0; nt < 4; nt++) {                                            \
            uint4 b1v, b3v;                                                         \
            lds128(b1v, bB + (uint32_t)(nt * 1024));                                \
            lds128(b3v, bB + (uint32_t)(8192 + nt * 1024));                         \
            _Pragma("unroll")                                                       \
            for (int mt = 0; mt < 2; mt++) {                                        \
                mma8(acc1[mt][nt], alo[mt].x, ahi[mt].x, alo[mt].y, ahi[mt].y, b1v.x, b1v.y); \
                mma8(acc1[mt][nt], alo[mt].z, ahi[mt].z, alo[mt].w, ahi[mt].w, b1v.z, b1v.w); \
                mma8(acc3[mt][nt], alo[mt].x, ahi[mt].x, alo[mt].y, ahi[mt].y, b3v.x, b3v.y); \
                mma8(acc3[mt][nt], alo[mt].z, ahi[mt].z, alo[mt].w, ahi[mt].w, b3v.z, b3v.w); \
            }                                                                       \
        }                                                                           \
    }                                                                               \
} while (0)

    float acc1[2][4][4], acc3[2][4][4];
#pragma unroll
    for (int mt = 0; mt < 2; mt++)
#pragma unroll
        for (int nt = 0; nt < 4; nt++)
#pragma unroll
            for (int i = 0; i < 4; i++) { acc1[mt][nt][i] = 0.f; acc3[mt][nt][i] = 0.f; }

    LOAD13(0u, 0);
#pragma unroll
    for (int i = 0; i < 4; i++) { pA[i] += 32; pB1[i] += 32; pB3[i] += 32; }

    const int NT = HDIM / 32;   // 32 (even)
    for (int t = 0; t < NT; t += 2) {
        CP_WAIT0();
        __syncthreads();
        LOAD13(24576u, 0);
        COMPUTE13(0u);
        CP_WAIT0();
        __syncthreads();
        if (t + 2 < NT) LOAD13(0u, 32);
        COMPUTE13(24576u);
#pragma unroll
        for (int i = 0; i < 4; i++) { pA[i] += 64; pB1[i] += 64; pB3[i] += 64; }
    }

    // epilogue: shfl-pack to phys-contiguous float4 stores (bypasses perm16)
    {
        const int jj = (qc & 1) * 2 + (qc >> 1);
        const bool low = (qc < 2);
#pragma unroll
        for (int mt = 0; mt < 2; mt++) {
#pragma unroll
            for (int h = 0; h < 2; h++) {
                int m = m0 + rq * 32 + mt * 16 + qr + 8 * h;
                bool ok = (m < cnt);
                float* hrow = g_h + ((size_t)e * T_TOK + m) * FDIM + n0 + cf * 32;
#pragma unroll
                for (int k = 0; k < 2; k++) {
                    float v00 = silu_mul_tf32(acc1[mt][2*k  ][2*h  ], acc3[mt][2*k  ][2*h  ]);
                    float v01 = silu_mul_tf32(acc1[mt][2*k  ][2*h+1], acc3[mt][2*k  ][2*h+1]);
                    float v10 = silu_mul_tf32(acc1[mt][2*k+1][2*h  ], acc3[mt][2*k+1][2*h  ]);
                    float v11 = silu_mul_tf32(acc1[mt][2*k+1][2*h+1], acc3[mt][2*k+1][2*h+1]);
                    float r0 = __shfl_xor_sync(0xffffffffu, low ? v01 : v00, 2);
                    float r1 = __shfl_xor_sync(0xffffffffu, low ? v11 : v10, 2);
                    float4 o;
                    if (low) { o.x = v00; o.y = r0;  o.z = v10; o.w = r1;  }
                    else     { o.x = r0;  o.y = v01; o.z = r1;  o.w = v11; }
                    if (ok) *(float4*)(hrow + k * 16 + 4 * jj) = o;
                }
            }
        }
    }
#undef LOAD13
#undef COMPUTE13
}

// =====================================================================
// GEMM2: y += wt * (h @ W2).  BM=64, BN=128, BK=32, 128 thr (2m x 2n).
// Warp: 32r x 64c. smem/stage (24KB): A[0,8K) B[8K,24K). 2 stages, wait0.
// =====================================================================
__global__ void __launch_bounds__(128, 4)
moe_gemm2(float* __restrict__ y)
{
    const int e   = blockIdx.z;
    const int cnt = g_cnt[e];
    const int m0  = blockIdx.x * 64;
    if (m0 >= cnt) return;
    const int n0  = blockIdx.y * 128;

    extern __shared__ char dsm[];
    const uint32_t sb = (smem_u32(dsm) + 127u) & ~127u;
    __shared__ const float* s_arow[64];

    const int tid  = threadIdx.x;
    const int warp = tid >> 5;
    const int lane = tid & 31;
    const int qr   = lane >> 2;
    const int qc   = lane & 3;
    const int rq   = warp & 1;
    const int cf   = warp >> 1;

    if (tid < 64) {
        int mm = min(m0 + tid, cnt - 1);
        s_arow[tid] = g_h + ((size_t)e * T_TOK + mm) * FDIM;
    }
    __syncthreads();

    const float* bb = g_w2t + (size_t)e * HDIM * FDIM + (size_t)n0 * FDIM;

    const int ch = tid & 7;
    const int rr = tid >> 3;        // 0..15
    const float* pA[4]; uint32_t dA[4];
#pragma unroll
    for (int i = 0; i < 4; i++) {
        int row = i * 16 + rr;      // 0..63
        pA[i] = s_arow[row] + ch * 4;
        dA[i] = sb + swoff(row, ch);
    }
    const float* pB[8]; uint32_t dB[8];
#pragma unroll
    for (int i = 0; i < 8; i++) {
        int row = i * 16 + rr;      // 0..127
        pB[i] = bb + (size_t)row * FDIM + ch * 4;
        dB[i] = sb + 8192u + swoff(row, ch);
    }

    const uint32_t swsel = (uint32_t)((qc ^ ((qr & 1) << 2)) << 4);
    const uint32_t aBase = sb + (uint32_t)((rq * 32 + qr) << 7) + swsel;
    const uint32_t bBase = sb + 8192u + (uint32_t)((cf * 64 + qr) << 7) + swsel;

#define LOAD2(stc_, ko_) do {                                             \
    _Pragma("unroll")                                                     \
    for (int i_ = 0; i_ < 4; i_++)                                        \
        CP_ASYNC16(dA[i_] + (stc_), pA[i_] + (ko_));                      \
    _Pragma("unroll")                                                     \
    for (int i_ = 0; i_ < 8; i_++)                                        \
        CP_ASYNC16(dB[i_] + (stc_), pB[i_] + (ko_));                      \
    CP_COMMIT();                                                          \
} while (0)

#define COMPUTE2(stc_) do {                                                         \
    const uint32_t aS0 = aBase + (stc_), bS0 = bBase + (stc_);                      \
    _Pragma("unroll")                                                               \
    for (int s = 0; s < 2; s++) {                                                   \
        const uint32_t aA = s ? (aS0 ^ 64u) : aS0;                                  \
        const uint32_t bB = s ? (bS0 ^ 64u) : bS0;                                  \
        uint4 alo[2], ahi[2];                                                       \
        lds128(alo[0], aA);           lds128(ahi[0], aA + 1024u);                   \
        lds128(alo[1], aA + 2048u);   lds128(ahi[1], aA + 3072u);                   \
        _Pragma("unroll")                                                           \
        for (int nt = 0; nt < 8; nt++) {                                            \
            uint4 bv;                                                               \
            lds128(bv, bB + (uint32_t)(nt * 1024));                                 \
            _Pragma("unroll")                                                       \
            for (int mt = 0; mt < 2; mt++) {                                        \
                mma8(acc[mt][nt], alo[mt].x, ahi[mt].x, alo[mt].y, ahi[mt].y, bv.x, bv.y); \
                mma8(acc[mt][nt], alo[mt].z, ahi[mt].z, alo[mt].w, ahi[mt].w, bv.z, bv.w); \
            }                                                                       \
        }                                                                           \
    }                                                                               \
} while (0)

    float acc[2][8][4];
#pragma unroll
    for (int mt = 0; mt < 2; mt++)
#pragma unroll
        for (int nt = 0; nt < 8; nt++)
#pragma unroll
            for (int i = 0; i < 4; i++) acc[mt][nt][i] = 0.f;

    LOAD2(0u, 0);
#pragma unroll
    for (int i = 0; i < 4; i++) pA[i] += 32;
#pragma unroll
    for (int i = 0; i < 8; i++) pB[i] += 32;

    const int NT = FDIM / 32;   // 64 (even)
    for (int t = 0; t < NT; t += 2) {
        CP_WAIT0();
        __syncthreads();
        LOAD2(24576u, 0);
        COMPUTE2(0u);
        CP_WAIT0();
        __syncthreads();
        if (t + 2 < NT) LOAD2(0u, 32);
        COMPUTE2(24576u);
#pragma unroll
        for (int i = 0; i < 4; i++) pA[i] += 64;
#pragma unroll
        for (int i = 0; i < 8; i++) pB[i] += 64;
    }

    // epilogue: y[tok] += wt * D (REDG atomics - measured cheap)
#pragma unroll
    for (int mt = 0; mt < 2; mt++) {
#pragma unroll
        for (int h = 0; h < 2; h++) {
            int m = m0 + rq * 32 + mt * 16 + qr + 8 * h;
            if (m >= cnt) continue;
            float w   = g_wt [e * T_TOK + m];
            int   tok = g_tok[e * T_TOK + m];
            float* yrow = y + (size_t)tok * HDIM + n0 + cf * 64;
#pragma unroll
            for (int nt = 0; nt < 8; nt++) {
#pragma unroll
                for (int b = 0; b < 2; b++)
                    atomicAdd(yrow + nt * 8 + qc * 2 + b, w * acc[mt][nt][2 * h + b]);
            }
        }
    }
#undef LOAD2
#undef COMPUTE2
}

// ---------------- launch ----------------
extern "C" void kernel_launch(void* const* d_in, const int* in_sizes, int n_in,
                              void* d_out, int out_size)
{
    const float* x  = (const float*)d_in[0];   // [2,2048,1024]
    const float* gw = (const float*)d_in[1];   // [8,1024]
    const float* w1 = (const float*)d_in[2];   // [8,1024,2048]
    const float* w3 = (const float*)d_in[3];   // [8,1024,2048]
    const float* w2 = (const float*)d_in[4];   // [8,2048,1024]
    float* out = (float*)d_out;

    const int SMEM = 2 * 24576 + 128;   // 49280 -> 4 CTAs/SM
    cudaFuncSetAttribute(moe_gemm13, cudaFuncAttributeMaxDynamicSharedMemorySize, SMEM);
    cudaFuncSetAttribute(moe_gemm2,  cudaFuncAttributeMaxDynamicSharedMemorySize, SMEM);

    cudaMemsetAsync(out, 0, (size_t)T_TOK * HDIM * sizeof(float));
    init_counts<<<1, 32>>>();

    int write_logits = (out_size >= T_TOK * HDIM + T_TOK * NEXP) ? 1 : 0;
    router_kernel<<<T_TOK / 4, 128>>>(x, gw, out + (size_t)T_TOK * HDIM, write_logits);

    prepass_kernel<<<dim3(1024, 25), 256>>>(x, w1, w3, w2);

    moe_gemm13<<<dim3(T_TOK / 64, FDIM / 64, NEXP), 128, SMEM>>>();
    moe_gemm2 <<<dim3(T_TOK / 64, HDIM / 128, NEXP), 128, SMEM>>>(out);
}

// round 16
// speedup vs baseline: 1.0906x; 1.0099x over previous
#include <cuda_runtime.h>
#include <stdint.h>
#include <stddef.h>

#define T_TOK 4096
#define HDIM  1024
#define FDIM  2048
#define NEXP  8
#define MAXBLK 136   // 8192/64 + 8 (padded per-expert m-blocks upper bound)

// ---------------- scratch (__device__ globals: alloc-free) ----------------
__device__ int   g_cnt[NEXP];
__device__ int   g_off[NEXP + 1];                      // padded prefix (units: rows)
__device__ int   g_tok[NEXP * T_TOK];
__device__ float g_wt [NEXP * T_TOK];
__device__ float g_h  [(size_t)NEXP * T_TOK * FDIM];   // silu(XW1)*XW3, tf32, k-perm
__device__ float g_xr [(size_t)T_TOK * HDIM];          // x tf32-rounded, k-perm
__device__ float g_w1t[(size_t)NEXP * FDIM * HDIM];    // w1^T [E][F][H], k-perm
__device__ float g_w3t[(size_t)NEXP * FDIM * HDIM];    // w3^T [E][F][H], k-perm
__device__ float g_w2t[(size_t)NEXP * HDIM * FDIM];    // w2^T [E][H][F], k-perm

// ---------------- helpers ----------------
__device__ __forceinline__ uint32_t smem_u32(const void* p) {
    uint32_t a;
    asm("{ .reg .u64 t; cvta.to.shared.u64 t, %1; cvt.u32.u64 %0, t; }" : "=r"(a) : "l"(p));
    return a;
}
__device__ __forceinline__ float rna_tf32(float f) {
    uint32_t r;
    asm("cvt.rna.tf32.f32 %0, %1;" : "=r"(r) : "f"(f));
    return __uint_as_float(r);
}
// smem offset: row stride 128B (32 floats), 8 chunks of 16B, xor-swizzled
__device__ __forceinline__ uint32_t swoff(int row, int chunk) {
    return (uint32_t)(row * 128 + ((chunk ^ ((row & 1) << 2)) << 4));
}

#define CP_ASYNC16(dst, src) \
    asm volatile("cp.async.cg.shared.global [%0], [%1], 16;\n" :: "r"(dst), "l"(src))
#define CP_COMMIT() asm volatile("cp.async.commit_group;\n")
#define CP_WAIT0()  asm volatile("cp.async.wait_group 0;\n")

__device__ __forceinline__ void lds128(uint4& v, uint32_t addr) {
    asm volatile("ld.shared.v4.b32 {%0,%1,%2,%3}, [%4];"
                 : "=r"(v.x), "=r"(v.y), "=r"(v.z), "=r"(v.w) : "r"(addr));
}
__device__ __forceinline__ void mma8(float* d, uint32_t a0, uint32_t a1, uint32_t a2,
                                     uint32_t a3, uint32_t b0, uint32_t b1) {
    asm volatile(
        "mma.sync.aligned.m16n8k8.row.col.f32.tf32.tf32.f32 "
        "{%0,%1,%2,%3}, {%4,%5,%6,%7}, {%8,%9}, {%0,%1,%2,%3};\n"
        : "+f"(d[0]), "+f"(d[1]), "+f"(d[2]), "+f"(d[3])
        : "r"(a0), "r"(a1), "r"(a2), "r"(a3), "r"(b0), "r"(b1));
}
__device__ __forceinline__ float silu_mul_tf32(float d1, float d3) {
    return rna_tf32(d1 / (1.f + __expf(-d1)) * d3);
}

// ---------------- init ----------------
__global__ void init_counts() {
    if (threadIdx.x < NEXP) g_cnt[threadIdx.x] = 0;
}

// ---------------- router ----------------
__global__ void router_kernel(const float* __restrict__ x,
                              const float* __restrict__ gw,
                              float* __restrict__ logits_out,
                              int write_logits)
{
    int tok  = (blockIdx.x * blockDim.x + threadIdx.x) >> 5;
    int lane = threadIdx.x & 31;
    if (tok >= T_TOK) return;
    const float* xr = x + (size_t)tok * HDIM;

    float acc[NEXP];
#pragma unroll
    for (int e = 0; e < NEXP; e++) acc[e] = 0.f;
    for (int h = lane; h < HDIM; h += 32) {
        float xv = xr[h];
#pragma unroll
        for (int e = 0; e < NEXP; e++) acc[e] = fmaf(xv, gw[e * HDIM + h], acc[e]);
    }
#pragma unroll
    for (int e = 0; e < NEXP; e++) {
#pragma unroll
        for (int off = 16; off > 0; off >>= 1)
            acc[e] += __shfl_xor_sync(0xffffffffu, acc[e], off);
    }
    if (lane == 0) {
        if (write_logits) {
#pragma unroll
            for (int e = 0; e < NEXP; e++) logits_out[tok * NEXP + e] = acc[e];
        }
        float mx = acc[0];
#pragma unroll
        for (int e = 1; e < NEXP; e++) mx = fmaxf(mx, acc[e]);
        float p[NEXP], s = 0.f;
#pragma unroll
        for (int e = 0; e < NEXP; e++) { p[e] = __expf(acc[e] - mx); s += p[e]; }
        float inv = 1.f / s;
#pragma unroll
        for (int e = 0; e < NEXP; e++) p[e] *= inv;

        int i1 = 0; float m1 = p[0];
#pragma unroll
        for (int e = 1; e < NEXP; e++) if (p[e] > m1) { m1 = p[e]; i1 = e; }
        int i2 = -1; float m2 = -1.f;
#pragma unroll
        for (int e = 0; e < NEXP; e++) {
            if (e == i1) continue;
            if (p[e] > m2) { m2 = p[e]; i2 = e; }
        }
        int pos1 = atomicAdd(&g_cnt[i1], 1);
        g_tok[i1 * T_TOK + pos1] = tok;  g_wt[i1 * T_TOK + pos1] = m1;
        int pos2 = atomicAdd(&g_cnt[i2], 1);
        g_tok[i2 * T_TOK + pos2] = tok;  g_wt[i2 * T_TOK + pos2] = m2;
    }
}

// ---------------- router post: padded prefix for compact grid -------------
__global__ void router_post() {
    if (threadIdx.x == 0) {
        int off = 0;
#pragma unroll
        for (int e = 0; e < NEXP; e++) {
            g_off[e] = off;
            off += ((g_cnt[e] + 63) & ~63);
        }
        g_off[NEXP] = off;
    }
}

// ---------------- fused pre-pass (R12 config: (1024,25), 2 tiles) ---------
__global__ void prepass_kernel(const float* __restrict__ x,
                               const float* __restrict__ w1,
                               const float* __restrict__ w3,
                               const float* __restrict__ w2)
{
    const int by = blockIdx.y;
    const int bx = blockIdx.x;
    if (by == 24) {
        int base = (bx * 256 + threadIdx.x) * 16;
#pragma unroll
        for (int q = 0; q < 4; q++) {
            int p = base + q * 4;
            int grp = p & ~15, j = (p >> 2) & 3;
            float4 o;
            o.x = rna_tf32(x[grp + j]);
            o.y = rna_tf32(x[grp + 4 + j]);
            o.z = rna_tf32(x[grp + 8 + j]);
            o.w = rna_tf32(x[grp + 12 + j]);
            *(float4*)(g_xr + p) = o;
        }
        return;
    }

    __shared__ float t[2][32][33];
    const float* in;
    float* out;
    int K, N, n0, k0;
    if (by < 16) {
        K = HDIM; N = FDIM;
        int e = by & 7;
        in  = ((by < 8) ? w1 : w3) + (size_t)e * K * N;
        out = ((by < 8) ? g_w1t : g_w3t) + (size_t)e * K * N;
        n0 = (bx & 63) * 32; k0 = (bx >> 6) * 64;
    } else {
        K = FDIM; N = HDIM;
        int e = by - 16;
        in  = w2 + (size_t)e * K * N;
        out = g_w2t + (size_t)e * K * N;
        n0 = (bx & 31) * 32; k0 = (bx >> 5) * 64;
    }

    int kr = threadIdx.x >> 3;            // 0..31
    int nc = (threadIdx.x & 7) * 4;
    float4 v0 = *(const float4*)(in + (size_t)(k0 + kr) * N + n0 + nc);
    float4 v1 = *(const float4*)(in + (size_t)(k0 + 32 + kr) * N + n0 + nc);
    t[0][kr][nc] = v0.x; t[0][kr][nc + 1] = v0.y; t[0][kr][nc + 2] = v0.z; t[0][kr][nc + 3] = v0.w;
    t[1][kr][nc] = v1.x; t[1][kr][nc + 1] = v1.y; t[1][kr][nc + 2] = v1.z; t[1][kr][nc + 3] = v1.w;
    __syncthreads();

    int nr = threadIdx.x >> 3;
    int c  = threadIdx.x & 7;
    int g  = (c >> 2) * 16, j = c & 3;
#pragma unroll
    for (int q = 0; q < 2; q++) {
        float4 o;
        o.x = rna_tf32(t[q][g + j     ][nr]);
        o.y = rna_tf32(t[q][g + 4 + j ][nr]);
        o.z = rna_tf32(t[q][g + 8 + j ][nr]);
        o.w = rna_tf32(t[q][g + 12 + j][nr]);
        *(float4*)(out + (size_t)(n0 + nr) * K + k0 + q * 32 + g + 4 * j) = o;
    }
}

// map a global 64-row block id -> (expert, m0); returns false if padding/out
__device__ __forceinline__ bool map_block(int gb, int& e, int& m0, int& cnt) {
    int row = gb * 64;
    if (row >= g_off[NEXP]) return false;
    e = 0;
#pragma unroll
    for (int i = 1; i < NEXP; i++) if (row >= g_off[i]) e = i;
    m0 = row - g_off[e];
    cnt = g_cnt[e];
    return (m0 < cnt);
}

// =====================================================================
// GEMM13 fused: h = silu(Xg @ W1) * (Xg @ W3)
// BM=64, BN=64, BK=32, 128 thr (4 warps 2m x 2n). Warp: 32r x 32c x 2 mats.
// smem/stage (24KB): A[0,8K) B1[8K,16K) B3[16K,24K). 2 stages, wait0.
// 4 CTAs/SM. Compact grid: (MAXBLK, 32).
// =====================================================================
__global__ void __launch_bounds__(128, 4)
moe_gemm13()
{
    int e, m0, cnt;
    if (!map_block(blockIdx.x, e, m0, cnt)) return;
    const int n0 = blockIdx.y * 64;

    extern __shared__ char dsm[];
    const uint32_t sb = (smem_u32(dsm) + 127u) & ~127u;
    __shared__ const float* s_arow[64];

    const int tid  = threadIdx.x;
    const int warp = tid >> 5;
    const int lane = tid & 31;
    const int qr   = lane >> 2;
    const int qc   = lane & 3;
    const int rq   = warp & 1;     // 2 warps in M
    const int cf   = warp >> 1;    // 2 warps in N

    if (tid < 64) {
        int mm = min(m0 + tid, cnt - 1);
        s_arow[tid] = g_xr + (size_t)g_tok[e * T_TOK + mm] * HDIM;
    }
    __syncthreads();

    const float* b1b = g_w1t + (size_t)e * FDIM * HDIM + (size_t)n0 * HDIM;
    const float* b3b = g_w3t + (size_t)e * FDIM * HDIM + (size_t)n0 * HDIM;

    const int ch  = tid & 7;
    const int rr  = tid >> 3;       // 0..15
    const float* pA[4]; uint32_t dA[4];
    const float* pB1[4]; const float* pB3[4]; uint32_t dB[4];
#pragma unroll
    for (int i = 0; i < 4; i++) {
        int row = i * 16 + rr;      // 0..63
        pA[i]  = s_arow[row] + ch * 4;
        dA[i]  = sb + swoff(row, ch);
        pB1[i] = b1b + (size_t)row * HDIM + ch * 4;
        pB3[i] = b3b + (size_t)row * HDIM + ch * 4;
        dB[i]  = sb + 8192u + swoff(row, ch);
    }

    const uint32_t swsel = (uint32_t)((qc ^ ((qr & 1) << 2)) << 4);
    const uint32_t aBase = sb + (uint32_t)((rq * 32 + qr) << 7) + swsel;
    const uint32_t bBase = sb + 8192u + (uint32_t)((cf * 32 + qr) << 7) + swsel;

#define LOAD13(stc_, ko_) do {                                            \
    _Pragma("unroll")                                                     \
    for (int i_ = 0; i_ < 4; i_++) {                                      \
        CP_ASYNC16(dA[i_] + (stc_),         pA[i_]  + (ko_));             \
        CP_ASYNC16(dB[i_] + (stc_),         pB1[i_] + (ko_));             \
        CP_ASYNC16(dB[i_] + 8192u + (stc_), pB3[i_] + (ko_));             \
    }                                                                     \
    CP_COMMIT();                                                          \
} while (0)

#define COMPUTE13(stc_) do {                                                        \
    const uint32_t aS0 = aBase + (stc_), bS0 = bBase + (stc_);                      \
    _Pragma("unroll")                                                               \
    for (int s = 0; s < 2; s++) {                                                   \
        const uint32_t aA = s ? (aS0 ^ 64u) : aS0;                                  \
        const uint32_t bB = s ? (bS0 ^ 64u) : bS0;                                  \
        uint4 alo[2], ahi[2];                                                       \
        lds128(alo[0], aA);           lds128(ahi[0], aA + 1024u);                   \
        lds128(alo[1], aA + 2048u);   lds128(ahi[1], aA + 3072u);                   \
        _Pragma("unroll")                                                           \
        for (int nt = 0; nt < 4; nt++) {                                            \
            uint4 b1v, b3v;                                                         \
            lds128(b1v, bB + (uint32_t)(nt * 1024));                                \
            lds128(b3v, bB + (uint32_t)(8192 + nt * 1024));                         \
            _Pragma("unroll")                                                       \
            for (int mt = 0; mt < 2; mt++) {                                        \
                mma8(acc1[mt][nt], alo[mt].x, ahi[mt].x, alo[mt].y, ahi[mt].y, b1v.x, b1v.y); \
                mma8(acc1[mt][nt], alo[mt].z, ahi[mt].z, alo[mt].w, ahi[mt].w, b1v.z, b1v.w); \
                mma8(acc3[mt][nt], alo[mt].x, ahi[mt].x, alo[mt].y, ahi[mt].y, b3v.x, b3v.y); \
                mma8(acc3[mt][nt], alo[mt].z, ahi[mt].z, alo[mt].w, ahi[mt].w, b3v.z, b3v.w); \
            }                                                                       \
        }                                                                           \
    }                                                                               \
} while (0)

    float acc1[2][4][4], acc3[2][4][4];
#pragma unroll
    for (int mt = 0; mt < 2; mt++)
#pragma unroll
        for (int nt = 0; nt < 4; nt++)
#pragma unroll
            for (int i = 0; i < 4; i++) { acc1[mt][nt][i] = 0.f; acc3[mt][nt][i] = 0.f; }

    LOAD13(0u, 0);
#pragma unroll
    for (int i = 0; i < 4; i++) { pA[i] += 32; pB1[i] += 32; pB3[i] += 32; }

    const int NT = HDIM / 32;   // 32 (even)
    for (int t = 0; t < NT; t += 2) {
        CP_WAIT0();
        __syncthreads();
        LOAD13(24576u, 0);
        COMPUTE13(0u);
        CP_WAIT0();
        __syncthreads();
        if (t + 2 < NT) LOAD13(0u, 32);
        COMPUTE13(24576u);
#pragma unroll
        for (int i = 0; i < 4; i++) { pA[i] += 64; pB1[i] += 64; pB3[i] += 64; }
    }

    // epilogue: shfl-pack to phys-contiguous float4 stores (bypasses perm16)
    {
        const int jj = (qc & 1) * 2 + (qc >> 1);
        const bool low = (qc < 2);
#pragma unroll
        for (int mt = 0; mt < 2; mt++) {
#pragma unroll
            for (int h = 0; h < 2; h++) {
                int m = m0 + rq * 32 + mt * 16 + qr + 8 * h;
                bool ok = (m < cnt);
                float* hrow = g_h + ((size_t)e * T_TOK + m) * FDIM + n0 + cf * 32;
#pragma unroll
                for (int k = 0; k < 2; k++) {
                    float v00 = silu_mul_tf32(acc1[mt][2*k  ][2*h  ], acc3[mt][2*k  ][2*h  ]);
                    float v01 = silu_mul_tf32(acc1[mt][2*k  ][2*h+1], acc3[mt][2*k  ][2*h+1]);
                    float v10 = silu_mul_tf32(acc1[mt][2*k+1][2*h  ], acc3[mt][2*k+1][2*h  ]);
                    float v11 = silu_mul_tf32(acc1[mt][2*k+1][2*h+1], acc3[mt][2*k+1][2*h+1]);
                    float r0 = __shfl_xor_sync(0xffffffffu, low ? v01 : v00, 2);
                    float r1 = __shfl_xor_sync(0xffffffffu, low ? v11 : v10, 2);
                    float4 o;
                    if (low) { o.x = v00; o.y = r0;  o.z = v10; o.w = r1;  }
                    else     { o.x = r0;  o.y = v01; o.z = r1;  o.w = v11; }
                    if (ok) *(float4*)(hrow + k * 16 + 4 * jj) = o;
                }
            }
        }
    }
#undef LOAD13
#undef COMPUTE13
}

// =====================================================================
// GEMM2: y += wt * (h @ W2).  BM=64, BN=128, BK=32, 128 thr (2m x 2n).
// Warp: 32r x 64c. smem/stage (24KB): A[0,8K) B[8K,24K). 2 stages, wait0.
// Compact grid: (MAXBLK, 8).
// =====================================================================
__global__ void __launch_bounds__(128, 4)
moe_gemm2(float* __restrict__ y)
{
    int e, m0, cnt;
    if (!map_block(blockIdx.x, e, m0, cnt)) return;
    const int n0 = blockIdx.y * 128;

    extern __shared__ char dsm[];
    const uint32_t sb = (smem_u32(dsm) + 127u) & ~127u;
    __shared__ const float* s_arow[64];

    const int tid  = threadIdx.x;
    const int warp = tid >> 5;
    const int lane = tid & 31;
    const int qr   = lane >> 2;
    const int qc   = lane & 3;
    const int rq   = warp & 1;
    const int cf   = warp >> 1;

    if (tid < 64) {
        int mm = min(m0 + tid, cnt - 1);
        s_arow[tid] = g_h + ((size_t)e * T_TOK + mm) * FDIM;
    }
    __syncthreads();

    const float* bb = g_w2t + (size_t)e * HDIM * FDIM + (size_t)n0 * FDIM;

    const int ch = tid & 7;
    const int rr = tid >> 3;        // 0..15
    const float* pA[4]; uint32_t dA[4];
#pragma unroll
    for (int i = 0; i < 4; i++) {
        int row = i * 16 + rr;      // 0..63
        pA[i] = s_arow[row] + ch * 4;
        dA[i] = sb + swoff(row, ch);
    }
    const float* pB[8]; uint32_t dB[8];
#pragma unroll
    for (int i = 0; i < 8; i++) {
        int row = i * 16 + rr;      // 0..127
        pB[i] = bb + (size_t)row * FDIM + ch * 4;
        dB[i] = sb + 8192u + swoff(row, ch);
    }

    const uint32_t swsel = (uint32_t)((qc ^ ((qr & 1) << 2)) << 4);
    const uint32_t aBase = sb + (uint32_t)((rq * 32 + qr) << 7) + swsel;
    const uint32_t bBase = sb + 8192u + (uint32_t)((cf * 64 + qr) << 7) + swsel;

#define LOAD2(stc_, ko_) do {                                             \
    _Pragma("unroll")                                                     \
    for (int i_ = 0; i_ < 4; i_++)                                        \
        CP_ASYNC16(dA[i_] + (stc_), pA[i_] + (ko_));                      \
    _Pragma("unroll")                                                     \
    for (int i_ = 0; i_ < 8; i_++)                                        \
        CP_ASYNC16(dB[i_] + (stc_), pB[i_] + (ko_));                      \
    CP_COMMIT();                                                          \
} while (0)

#define COMPUTE2(stc_) do {                                                         \
    const uint32_t aS0 = aBase + (stc_), bS0 = bBase + (stc_);                      \
    _Pragma("unroll")                                                               \
    for (int s = 0; s < 2; s++) {                                                   \
        const uint32_t aA = s ? (aS0 ^ 64u) : aS0;                                  \
        const uint32_t bB = s ? (bS0 ^ 64u) : bS0;                                  \
        uint4 alo[2], ahi[2];                                                       \
        lds128(alo[0], aA);           lds128(ahi[0], aA + 1024u);                   \
        lds128(alo[1], aA + 2048u);   lds128(ahi[1], aA + 3072u);                   \
        _Pragma("unroll")                                                           \
        for (int nt = 0; nt < 8; nt++) {                                            \
            uint4 bv;                                                               \
            lds128(bv, bB + (uint32_t)(nt * 1024));                                 \
            _Pragma("unroll")                                                       \
            for (int mt = 0; mt < 2; mt++) {                                        \
                mma8(acc[mt][nt], alo[mt].x, ahi[mt].x, alo[mt].y, ahi[mt].y, bv.x, bv.y); \
                mma8(acc[mt][nt], alo[mt].z, ahi[mt].z, alo[mt].w, ahi[mt].w, bv.z, bv.w); \
            }                                                                       \
        }                                                                           \
    }                                                                               \
} while (0)

    float acc[2][8][4];
#pragma unroll
    for (int mt = 0; mt < 2; mt++)
#pragma unroll
        for (int nt = 0; nt < 8; nt++)
#pragma unroll
            for (int i = 0; i < 4; i++) acc[mt][nt][i] = 0.f;

    LOAD2(0u, 0);
#pragma unroll
    for (int i = 0; i < 4; i++) pA[i] += 32;
#pragma unroll
    for (int i = 0; i < 8; i++) pB[i] += 32;

    const int NT = FDIM / 32;   // 64 (even)
    for (int t = 0; t < NT; t += 2) {
        CP_WAIT0();
        __syncthreads();
        LOAD2(24576u, 0);
        COMPUTE2(0u);
        CP_WAIT0();
        __syncthreads();
        if (t + 2 < NT) LOAD2(0u, 32);
        COMPUTE2(24576u);
#pragma unroll
        for (int i = 0; i < 4; i++) pA[i] += 64;
#pragma unroll
        for (int i = 0; i < 8; i++) pB[i] += 64;
    }

    // epilogue: y[tok] += wt * D (REDG atomics - measured cheap)
#pragma unroll
    for (int mt = 0; mt < 2; mt++) {
#pragma unroll
        for (int h = 0; h < 2; h++) {
            int m = m0 + rq * 32 + mt * 16 + qr + 8 * h;
            if (m >= cnt) continue;
            float w   = g_wt [e * T_TOK + m];
            int   tok = g_tok[e * T_TOK + m];
            float* yrow = y + (size_t)tok * HDIM + n0 + cf * 64;
#pragma unroll
            for (int nt = 0; nt < 8; nt++) {
#pragma unroll
                for (int b = 0; b < 2; b++)
                    atomicAdd(yrow + nt * 8 + qc * 2 + b, w * acc[mt][nt][2 * h + b]);
            }
        }
    }
#undef LOAD2
#undef COMPUTE2
}

// ---------------- launch ----------------
extern "C" void kernel_launch(void* const* d_in, const int* in_sizes, int n_in,
                              void* d_out, int out_size)
{
    const float* x  = (const float*)d_in[0];   // [2,2048,1024]
    const float* gw = (const float*)d_in[1];   // [8,1024]
    const float* w1 = (const float*)d_in[2];   // [8,1024,2048]
    const float* w3 = (const float*)d_in[3];   // [8,1024,2048]
    const float* w2 = (const float*)d_in[4];   // [8,2048,1024]
    float* out = (float*)d_out;

    const int SMEM = 2 * 24576 + 128;   // 49280 -> 4 CTAs/SM
    cudaFuncSetAttribute(moe_gemm13, cudaFuncAttributeMaxDynamicSharedMemorySize, SMEM);
    cudaFuncSetAttribute(moe_gemm2,  cudaFuncAttributeMaxDynamicSharedMemorySize, SMEM);

    cudaMemsetAsync(out, 0, (size_t)T_TOK * HDIM * sizeof(float));
    init_counts<<<1, 32>>>();

    int write_logits = (out_size >= T_TOK * HDIM + T_TOK * NEXP) ? 1 : 0;
    router_kernel<<<T_TOK / 4, 128>>>(x, gw, out + (size_t)T_TOK * HDIM, write_logits);
    router_post<<<1, 32>>>();

    prepass_kernel<<<dim3(1024, 25), 256>>>(x, w1, w3, w2);

    // compact grids: blockIdx.x spans padded global m-blocks (<= MAXBLK)
    moe_gemm13<<<dim3(MAXBLK, FDIM / 64), 128, SMEM>>>();
    moe_gemm2 <<<dim3(MAXBLK, HDIM / 128), 128, SMEM>>>(out);
}

// round 17
// speedup vs baseline: 1.1125x; 1.0201x over previous
#include <cuda_runtime.h>
#include <stdint.h>
#include <stddef.h>

#define T_TOK 4096
#define HDIM  1024
#define FDIM  2048
#define NEXP  8
#define MAXBLK 136   // 8192/64 + 8 (padded per-expert m-blocks upper bound)

// ---------------- scratch (__device__ globals: alloc-free) ----------------
__device__ int   g_cnt[NEXP];
__device__ int   g_tok[NEXP * T_TOK];
__device__ float g_wt [NEXP * T_TOK];
__device__ float g_h  [(size_t)NEXP * T_TOK * FDIM];   // silu(XW1)*XW3, tf32, k-perm
__device__ float g_xr [(size_t)T_TOK * HDIM];          // x tf32-rounded, k-perm
__device__ float g_w1t[(size_t)NEXP * FDIM * HDIM];    // w1^T [E][F][H], k-perm
__device__ float g_w3t[(size_t)NEXP * FDIM * HDIM];    // w3^T [E][F][H], k-perm
__device__ float g_w2t[(size_t)NEXP * HDIM * FDIM];    // w2^T [E][H][F], k-perm

// ---------------- helpers ----------------
__device__ __forceinline__ uint32_t smem_u32(const void* p) {
    uint32_t a;
    asm("{ .reg .u64 t; cvta.to.shared.u64 t, %1; cvt.u32.u64 %0, t; }" : "=r"(a) : "l"(p));
    return a;
}
__device__ __forceinline__ float rna_tf32(float f) {
    uint32_t r;
    asm("cvt.rna.tf32.f32 %0, %1;" : "=r"(r) : "f"(f));
    return __uint_as_float(r);
}
// smem offset: row stride 128B (32 floats), 8 chunks of 16B, xor-swizzled
__device__ __forceinline__ uint32_t swoff(int row, int chunk) {
    return (uint32_t)(row * 128 + ((chunk ^ ((row & 1) << 2)) << 4));
}

#define CP_ASYNC16(dst, src) \
    asm volatile("cp.async.cg.shared.global [%0], [%1], 16;\n" :: "r"(dst), "l"(src))
#define CP_COMMIT() asm volatile("cp.async.commit_group;\n")
#define CP_WAIT0()  asm volatile("cp.async.wait_group 0;\n")

__device__ __forceinline__ void lds128(uint4& v, uint32_t addr) {
    asm volatile("ld.shared.v4.b32 {%0,%1,%2,%3}, [%4];"
                 : "=r"(v.x), "=r"(v.y), "=r"(v.z), "=r"(v.w) : "r"(addr));
}
__device__ __forceinline__ void mma8(float* d, uint32_t a0, uint32_t a1, uint32_t a2,
                                     uint32_t a3, uint32_t b0, uint32_t b1) {
    asm volatile(
        "mma.sync.aligned.m16n8k8.row.col.f32.tf32.tf32.f32 "
        "{%0,%1,%2,%3}, {%4,%5,%6,%7}, {%8,%9}, {%0,%1,%2,%3};\n"
        : "+f"(d[0]), "+f"(d[1]), "+f"(d[2]), "+f"(d[3])
        : "r"(a0), "r"(a1), "r"(a2), "r"(a3), "r"(b0), "r"(b1));
}
__device__ __forceinline__ float silu_mul_tf32(float d1, float d3) {
    return rna_tf32(d1 / (1.f + __expf(-d1)) * d3);
}

// ---------------- init ----------------
__global__ void init_counts() {
    if (threadIdx.x < NEXP) g_cnt[threadIdx.x] = 0;
}

// ---------------- fused pre-pass + router ---------------------------------
// grid (1024, 26), block 256.
//  by in [0,8)  : w1 expert by         (K=1024, N=2048)  2 k-tiles/block
//  by in [8,16) : w3 expert by-8
//  by in [16,24): w2 expert by-16      (K=2048, N=1024)
//  by == 24     : x tf32-round+k-perm  16 floats/thread
//  by == 25     : router (bx<512, 8 warps = 8 tokens/block)
__global__ void prepass_kernel(const float* __restrict__ x,
                               const float* __restrict__ w1,
                               const float* __restrict__ w3,
                               const float* __restrict__ w2,
                               const float* __restrict__ gw,
                               float* __restrict__ logits_out,
                               int write_logits)
{
    const int by = blockIdx.y;
    const int bx = blockIdx.x;

    if (by == 25) {
        // ---- router slice ----
        if (bx >= T_TOK / 8) return;
        int warp = threadIdx.x >> 5;
        int lane = threadIdx.x & 31;
        int tok  = bx * 8 + warp;
        const float* xr = x + (size_t)tok * HDIM;

        float acc[NEXP];
#pragma unroll
        for (int e = 0; e < NEXP; e++) acc[e] = 0.f;
        for (int h = lane; h < HDIM; h += 32) {
            float xv = xr[h];
#pragma unroll
            for (int e = 0; e < NEXP; e++) acc[e] = fmaf(xv, gw[e * HDIM + h], acc[e]);
        }
#pragma unroll
        for (int e = 0; e < NEXP; e++) {
#pragma unroll
            for (int off = 16; off > 0; off >>= 1)
                acc[e] += __shfl_xor_sync(0xffffffffu, acc[e], off);
        }
        if (lane == 0) {
            if (write_logits) {
#pragma unroll
                for (int e = 0; e < NEXP; e++) logits_out[tok * NEXP + e] = acc[e];
            }
            float mx = acc[0];
#pragma unroll
            for (int e = 1; e < NEXP; e++) mx = fmaxf(mx, acc[e]);
            float p[NEXP], s = 0.f;
#pragma unroll
            for (int e = 0; e < NEXP; e++) { p[e] = __expf(acc[e] - mx); s += p[e]; }
            float inv = 1.f / s;
#pragma unroll
            for (int e = 0; e < NEXP; e++) p[e] *= inv;

            int i1 = 0; float m1 = p[0];
#pragma unroll
            for (int e = 1; e < NEXP; e++) if (p[e] > m1) { m1 = p[e]; i1 = e; }
            int i2 = -1; float m2 = -1.f;
#pragma unroll
            for (int e = 0; e < NEXP; e++) {
                if (e == i1) continue;
                if (p[e] > m2) { m2 = p[e]; i2 = e; }
            }
            int pos1 = atomicAdd(&g_cnt[i1], 1);
            g_tok[i1 * T_TOK + pos1] = tok;  g_wt[i1 * T_TOK + pos1] = m1;
            int pos2 = atomicAdd(&g_cnt[i2], 1);
            g_tok[i2 * T_TOK + pos2] = tok;  g_wt[i2 * T_TOK + pos2] = m2;
        }
        return;
    }

    if (by == 24) {
        int base = (bx * 256 + threadIdx.x) * 16;
#pragma unroll
        for (int q = 0; q < 4; q++) {
            int p = base + q * 4;
            int grp = p & ~15, j = (p >> 2) & 3;
            float4 o;
            o.x = rna_tf32(x[grp + j]);
            o.y = rna_tf32(x[grp + 4 + j]);
            o.z = rna_tf32(x[grp + 8 + j]);
            o.w = rna_tf32(x[grp + 12 + j]);
            *(float4*)(g_xr + p) = o;
        }
        return;
    }

    __shared__ float t[2][32][33];
    const float* in;
    float* out;
    int K, N, n0, k0;
    if (by < 16) {
        K = HDIM; N = FDIM;
        int e = by & 7;
        in  = ((by < 8) ? w1 : w3) + (size_t)e * K * N;
        out = ((by < 8) ? g_w1t : g_w3t) + (size_t)e * K * N;
        n0 = (bx & 63) * 32; k0 = (bx >> 6) * 64;
    } else {
        K = FDIM; N = HDIM;
        int e = by - 16;
        in  = w2 + (size_t)e * K * N;
        out = g_w2t + (size_t)e * K * N;
        n0 = (bx & 31) * 32; k0 = (bx >> 5) * 64;
    }

    int kr = threadIdx.x >> 3;            // 0..31
    int nc = (threadIdx.x & 7) * 4;
    float4 v0 = *(const float4*)(in + (size_t)(k0 + kr) * N + n0 + nc);
    float4 v1 = *(const float4*)(in + (size_t)(k0 + 32 + kr) * N + n0 + nc);
    t[0][kr][nc] = v0.x; t[0][kr][nc + 1] = v0.y; t[0][kr][nc + 2] = v0.z; t[0][kr][nc + 3] = v0.w;
    t[1][kr][nc] = v1.x; t[1][kr][nc + 1] = v1.y; t[1][kr][nc + 2] = v1.z; t[1][kr][nc + 3] = v1.w;
    __syncthreads();

    int nr = threadIdx.x >> 3;
    int c  = threadIdx.x & 7;
    int g  = (c >> 2) * 16, j = c & 3;
#pragma unroll
    for (int q = 0; q < 2; q++) {
        float4 o;
        o.x = rna_tf32(t[q][g + j     ][nr]);
        o.y = rna_tf32(t[q][g + 4 + j ][nr]);
        o.z = rna_tf32(t[q][g + 8 + j ][nr]);
        o.w = rna_tf32(t[q][g + 12 + j][nr]);
        *(float4*)(out + (size_t)(n0 + nr) * K + k0 + q * 32 + g + 4 * j) = o;
    }
}

// map a global 64-row block id -> (expert, m0) via inline padded prefix scan
__device__ __forceinline__ bool map_block(int gb, int& e, int& m0, int& cnt) {
    int row = gb * 64;
    int off = 0;
#pragma unroll
    for (int i = 0; i < NEXP; i++) {
        int ci = __ldg(&g_cnt[i]);
        int pi = (ci + 63) & ~63;
        if (row < off + pi) { e = i; m0 = row - off; cnt = ci; return (m0 < cnt); }
        off += pi;
    }
    return false;
}

// =====================================================================
// GEMM13 fused: h = silu(Xg @ W1) * (Xg @ W3)
// BM=64, BN=64, BK=32, 128 thr (4 warps 2m x 2n). Warp: 32r x 32c x 2 mats.
// smem/stage (24KB): A[0,8K) B1[8K,16K) B3[16K,24K). 2 stages, wait0.
// 4 CTAs/SM. Compact grid: (MAXBLK, 32).
// =====================================================================
__global__ void __launch_bounds__(128, 4)
moe_gemm13()
{
    int e, m0, cnt;
    if (!map_block(blockIdx.x, e, m0, cnt)) return;
    const int n0 = blockIdx.y * 64;

    extern __shared__ char dsm[];
    const uint32_t sb = (smem_u32(dsm) + 127u) & ~127u;
    __shared__ const float* s_arow[64];

    const int tid  = threadIdx.x;
    const int warp = tid >> 5;
    const int lane = tid & 31;
    const int qr   = lane >> 2;
    const int qc   = lane & 3;
    const int rq   = warp & 1;     // 2 warps in M
    const int cf   = warp >> 1;    // 2 warps in N

    if (tid < 64) {
        int mm = min(m0 + tid, cnt - 1);
        s_arow[tid] = g_xr + (size_t)g_tok[e * T_TOK + mm] * HDIM;
    }
    __syncthreads();

    const float* b1b = g_w1t + (size_t)e * FDIM * HDIM + (size_t)n0 * HDIM;
    const float* b3b = g_w3t + (size_t)e * FDIM * HDIM + (size_t)n0 * HDIM;

    const int ch  = tid & 7;
    const int rr  = tid >> 3;       // 0..15
    const float* pA[4]; uint32_t dA[4];
    const float* pB1[4]; const float* pB3[4]; uint32_t dB[4];
#pragma unroll
    for (int i = 0; i < 4; i++) {
        int row = i * 16 + rr;      // 0..63
        pA[i]  = s_arow[row] + ch * 4;
        dA[i]  = sb + swoff(row, ch);
        pB1[i] = b1b + (size_t)row * HDIM + ch * 4;
        pB3[i] = b3b + (size_t)row * HDIM + ch * 4;
        dB[i]  = sb + 8192u + swoff(row, ch);
    }

    const uint32_t swsel = (uint32_t)((qc ^ ((qr & 1) << 2)) << 4);
    const uint32_t aBase = sb + (uint32_t)((rq * 32 + qr) << 7) + swsel;
    const uint32_t bBase = sb + 8192u + (uint32_t)((cf * 32 + qr) << 7) + swsel;

#define LOAD13(stc_, ko_) do {                                            \
    _Pragma("unroll")                                                     \
    for (int i_ = 0; i_ < 4; i_++) {                                      \
        CP_ASYNC16(dA[i_] + (stc_),         pA[i_]  + (ko_));             \
        CP_ASYNC16(dB[i_] + (stc_),         pB1[i_] + (ko_));             \
        CP_ASYNC16(dB[i_] + 8192u + (stc_), pB3[i_] + (ko_));             \
    }                                                                     \
    CP_COMMIT();                                                          \
} while (0)

#define COMPUTE13(stc_) do {                                                        \
    const uint32_t aS0 = aBase + (stc_), bS0 = bBase + (stc_);                      \
    _Pragma("unroll")                                                               \
    for (int s = 0; s < 2; s++) {                                                   \
        const uint32_t aA = s ? (aS0 ^ 64u) : aS0;                                  \
        const uint32_t bB = s ? (bS0 ^ 64u) : bS0;                                  \
        uint4 alo[2], ahi[2];                                                       \
        lds128(alo[0], aA);           lds128(ahi[0], aA + 1024u);                   \
        lds128(alo[1], aA + 2048u);   lds128(ahi[1], aA + 3072u);                   \
        _Pragma("unroll")                                                           \
        for (int nt = 0; nt < 4; nt++) {                                            \
            uint4 b1v, b3v;                                                         \
            lds128(b1v, bB + (uint32_t)(nt * 1024));                                \
            lds128(b3v, bB + (uint32_t)(8192 + nt * 1024));                         \
            _Pragma("unroll")                                                       \
            for (int mt = 0; mt < 2; mt++) {                                        \
                mma8(acc1[mt][nt], alo[mt].x, ahi[mt].x, alo[mt].y, ahi[mt].y, b1v.x, b1v.y); \
                mma8(acc1[mt][nt], alo[mt].z, ahi[mt].z, alo[mt].w, ahi[mt].w, b1v.z, b1v.w); \
                mma8(acc3[mt][nt], alo[mt].x, ahi[mt].x, alo[mt].y, ahi[mt].y, b3v.x, b3v.y); \
                mma8(acc3[mt][nt], alo[mt].z, ahi[mt].z, alo[mt].w, ahi[mt].w, b3v.z, b3v.w); \
            }                                                                       \
        }                                                                           \
    }                                                                               \
} while (0)

    float acc1[2][4][4], acc3[2][4][4];
#pragma unroll
    for (int mt = 0; mt < 2; mt++)
#pragma unroll
        for (int nt = 0; nt < 4; nt++)
#pragma unroll
            for (int i = 0; i < 4; i++) { acc1[mt][nt][i] = 0.f; acc3[mt][nt][i] = 0.f; }

    LOAD13(0u, 0);
#pragma unroll
    for (int i = 0; i < 4; i++) { pA[i] += 32; pB1[i] += 32; pB3[i] += 32; }

    const int NT = HDIM / 32;   // 32 (even)
    for (int t = 0; t < NT; t += 2) {
        CP_WAIT0();
        __syncthreads();
        LOAD13(24576u, 0);
        COMPUTE13(0u);
        CP_WAIT0();
        __syncthreads();
        if (t + 2 < NT) LOAD13(0u, 32);
        COMPUTE13(24576u);
#pragma unroll
        for (int i = 0; i < 4; i++) { pA[i] += 64; pB1[i] += 64; pB3[i] += 64; }
    }

    // epilogue: shfl-pack to phys-contiguous float4 stores (bypasses perm16)
    {
        const int jj = (qc & 1) * 2 + (qc >> 1);
        const bool low = (qc < 2);
#pragma unroll
        for (int mt = 0; mt < 2; mt++) {
#pragma unroll
            for (int h = 0; h < 2; h++) {
                int m = m0 + rq * 32 + mt * 16 + qr + 8 * h;
                bool ok = (m < cnt);
                float* hrow = g_h + ((size_t)e * T_TOK + m) * FDIM + n0 + cf * 32;
#pragma unroll
                for (int k = 0; k < 2; k++) {
                    float v00 = silu_mul_tf32(acc1[mt][2*k  ][2*h  ], acc3[mt][2*k  ][2*h  ]);
                    float v01 = silu_mul_tf32(acc1[mt][2*k  ][2*h+1], acc3[mt][2*k  ][2*h+1]);
                    float v10 = silu_mul_tf32(acc1[mt][2*k+1][2*h  ], acc3[mt][2*k+1][2*h  ]);
                    float v11 = silu_mul_tf32(acc1[mt][2*k+1][2*h+1], acc3[mt][2*k+1][2*h+1]);
                    float r0 = __shfl_xor_sync(0xffffffffu, low ? v01 : v00, 2);
                    float r1 = __shfl_xor_sync(0xffffffffu, low ? v11 : v10, 2);
                    float4 o;
                    if (low) { o.x = v00; o.y = r0;  o.z = v10; o.w = r1;  }
                    else     { o.x = r0;  o.y = v01; o.z = r1;  o.w = v11; }
                    if (ok) *(float4*)(hrow + k * 16 + 4 * jj) = o;
                }
            }
        }
    }
#undef LOAD13
#undef COMPUTE13
}

// =====================================================================
// GEMM2: y += wt * (h @ W2).  BM=64, BN=128, BK=32, 128 thr (2m x 2n).
// Warp: 32r x 64c. smem/stage (24KB): A[0,8K) B[8K,24K). 2 stages, wait0.
// Compact grid: (MAXBLK, 8).
// =====================================================================
__global__ void __launch_bounds__(128, 4)
moe_gemm2(float* __restrict__ y)
{
    int e, m0, cnt;
    if (!map_block(blockIdx.x, e, m0, cnt)) return;
    const int n0 = blockIdx.y * 128;

    extern __shared__ char dsm[];
    const uint32_t sb = (smem_u32(dsm) + 127u) & ~127u;
    __shared__ const float* s_arow[64];

    const int tid  = threadIdx.x;
    const int warp = tid >> 5;
    const int lane = tid & 31;
    const int qr   = lane >> 2;
    const int qc   = lane & 3;
    const int rq   = warp & 1;
    const int cf   = warp >> 1;

    if (tid < 64) {
        int mm = min(m0 + tid, cnt - 1);
        s_arow[tid] = g_h + ((size_t)e * T_TOK + mm) * FDIM;
    }
    __syncthreads();

    const float* bb = g_w2t + (size_t)e * HDIM * FDIM + (size_t)n0 * FDIM;

    const int ch = tid & 7;
    const int rr = tid >> 3;        // 0..15
    const float* pA[4]; uint32_t dA[4];
#pragma unroll
    for (int i = 0; i < 4; i++) {
        int row = i * 16 + rr;      // 0..63
        pA[i] = s_arow[row] + ch * 4;
        dA[i] = sb + swoff(row, ch);
    }
    const float* pB[8]; uint32_t dB[8];
#pragma unroll
    for (int i = 0; i < 8; i++) {
        int row = i * 16 + rr;      // 0..127
        pB[i] = bb + (size_t)row * FDIM + ch * 4;
        dB[i] = sb + 8192u + swoff(row, ch);
    }

    const uint32_t swsel = (uint32_t)((qc ^ ((qr & 1) << 2)) << 4);
    const uint32_t aBase = sb + (uint32_t)((rq * 32 + qr) << 7) + swsel;
    const uint32_t bBase = sb + 8192u + (uint32_t)((cf * 64 + qr) << 7) + swsel;

#define LOAD2(stc_, ko_) do {                                             \
    _Pragma("unroll")                                                     \
    for (int i_ = 0; i_ < 4; i_++)                                        \
        CP_ASYNC16(dA[i_] + (stc_), pA[i_] + (ko_));                      \
    _Pragma("unroll")                                                     \
    for (int i_ = 0; i_ < 8; i_++)                                        \
        CP_ASYNC16(dB[i_] + (stc_), pB[i_] + (ko_));                      \
    CP_COMMIT();                                                          \
} while (0)

#define COMPUTE2(stc_) do {                                                         \
    const uint32_t aS0 = aBase + (stc_), bS0 = bBase + (stc_);                      \
    _Pragma("unroll")                                                               \
    for (int s = 0; s < 2; s++) {                                                   \
        const uint32_t aA = s ? (aS0 ^ 64u) : aS0;                                  \
        const uint32_t bB = s ? (bS0 ^ 64u) : bS0;                                  \
        uint4 alo[2], ahi[2];                                                       \
        lds128(alo[0], aA);           lds128(ahi[0], aA + 1024u);                   \
        lds128(alo[1], aA + 2048u);   lds128(ahi[1], aA + 3072u);                   \
        _Pragma("unroll")                                                           \
        for (int nt = 0; nt < 8; nt++) {                                            \
            uint4 bv;                                                               \
            lds128(bv, bB + (uint32_t)(nt * 1024));                                 \
            _Pragma("unroll")                                                       \
            for (int mt = 0; mt < 2; mt++) {                                        \
                mma8(acc[mt][nt], alo[mt].x, ahi[mt].x, alo[mt].y, ahi[mt].y, bv.x, bv.y); \
                mma8(acc[mt][nt], alo[mt].z, ahi[mt].z, alo[mt].w, ahi[mt].w, bv.z, bv.w); \
            }                                                                       \
        }                                                                           \
    }                                                                               \
} while (0)

    float acc[2][8][4];
#pragma unroll
    for (int mt = 0; mt < 2; mt++)
#pragma unroll
        for (int nt = 0; nt < 8; nt++)
#pragma unroll
            for (int i = 0; i < 4; i++) acc[mt][nt][i] = 0.f;

    LOAD2(0u, 0);
#pragma unroll
    for (int i = 0; i < 4; i++) pA[i] += 32;
#pragma unroll
    for (int i = 0; i < 8; i++) pB[i] += 32;

    const int NT = FDIM / 32;   // 64 (even)
    for (int t = 0; t < NT; t += 2) {
        CP_WAIT0();
        __syncthreads();
        LOAD2(24576u, 0);
        COMPUTE2(0u);
        CP_WAIT0();
        __syncthreads();
        if (t + 2 < NT) LOAD2(0u, 32);
        COMPUTE2(24576u);
#pragma unroll
        for (int i = 0; i < 4; i++) pA[i] += 64;
#pragma unroll
        for (int i = 0; i < 8; i++) pB[i] += 64;
    }

    // epilogue: y[tok] += wt * D (REDG atomics - measured cheap)
#pragma unroll
    for (int mt = 0; mt < 2; mt++) {
#pragma unroll
        for (int h = 0; h < 2; h++) {
            int m = m0 + rq * 32 + mt * 16 + qr + 8 * h;
            if (m >= cnt) continue;
            float w   = g_wt [e * T_TOK + m];
            int   tok = g_tok[e * T_TOK + m];
            float* yrow = y + (size_t)tok * HDIM + n0 + cf * 64;
#pragma unroll
            for (int nt = 0; nt < 8; nt++) {
#pragma unroll
                for (int b = 0; b < 2; b++)
                    atomicAdd(yrow + nt * 8 + qc * 2 + b, w * acc[mt][nt][2 * h + b]);
            }
        }
    }
#undef LOAD2
#undef COMPUTE2
}

// ---------------- launch ----------------
extern "C" void kernel_launch(void* const* d_in, const int* in_sizes, int n_in,
                              void* d_out, int out_size)
{
    const float* x  = (const float*)d_in[0];   // [2,2048,1024]
    const float* gw = (const float*)d_in[1];   // [8,1024]
    const float* w1 = (const float*)d_in[2];   // [8,1024,2048]
    const float* w3 = (const float*)d_in[3];   // [8,1024,2048]
    const float* w2 = (const float*)d_in[4];   // [8,2048,1024]
    float* out = (float*)d_out;

    const int SMEM = 2 * 24576 + 128;   // 49280 -> 4 CTAs/SM
    cudaFuncSetAttribute(moe_gemm13, cudaFuncAttributeMaxDynamicSharedMemorySize, SMEM);
    cudaFuncSetAttribute(moe_gemm2,  cudaFuncAttributeMaxDynamicSharedMemorySize, SMEM);

    cudaMemsetAsync(out, 0, (size_t)T_TOK * HDIM * sizeof(float));
    init_counts<<<1, 32>>>();

    int write_logits = (out_size >= T_TOK * HDIM + T_TOK * NEXP) ? 1 : 0;

    // ONE launch: weight transposes + x rounding + router (hidden under DRAM time)
    prepass_kernel<<<dim3(1024, 26), 256>>>(x, w1, w3, w2, gw,
                                            out + (size_t)T_TOK * HDIM, write_logits);

    // compact grids: blockIdx.x spans padded global m-blocks (<= MAXBLK)
    moe_gemm13<<<dim3(MAXBLK, FDIM / 64), 128, SMEM>>>();
    moe_gemm2 <<<dim3(MAXBLK, HDIM / 128), 128, SMEM>>>(out);
}